// round 13
// baseline (speedup 1.0000x reference)
#include <cuda_runtime.h>
#include <math.h>

// Problem constants
#define BATCH     16384
#define NUM_F     32
#define EMBED     64
#define NPAIRS    496          // 32*31/2
#define THREADS   256
#define ROWS_CTA  4

// ---- plain 256-bit load (sm_103 LDG.256), no cache hints ----
struct F8 { float v[8]; };

__device__ __forceinline__ F8 ldg256(const float* p) {
    unsigned r0,r1,r2,r3,r4,r5,r6,r7;
    asm("ld.global.nc.v8.b32 {%0,%1,%2,%3,%4,%5,%6,%7}, [%8];"
        : "=r"(r0),"=r"(r1),"=r"(r2),"=r"(r3),"=r"(r4),"=r"(r5),"=r"(r6),"=r"(r7)
        : "l"(p));
    F8 o;
    o.v[0]=__uint_as_float(r0); o.v[1]=__uint_as_float(r1);
    o.v[2]=__uint_as_float(r2); o.v[3]=__uint_as_float(r3);
    o.v[4]=__uint_as_float(r4); o.v[5]=__uint_as_float(r5);
    o.v[6]=__uint_as_float(r6); o.v[7]=__uint_as_float(r7);
    return o;
}

__device__ __forceinline__ float sum8(const F8& a) {
    return ((a.v[0]+a.v[1]) + (a.v[2]+a.v[3])) + ((a.v[4]+a.v[5]) + (a.v[6]+a.v[7]));
}

// x: [BATCH, 32, 64] f32  (2048 floats per row)
// out: [BATCH, 496] f32   -> row is 1984 bytes = 124 * float4 (16B aligned per row)
__global__ __launch_bounds__(THREADS, 6)
void opn_kernel(const float* __restrict__ x, float4* __restrict__ out)
{
    const int tid = threadIdx.x;
    const int b0  = blockIdx.x * ROWS_CTA;

    __shared__ float s[ROWS_CTA][NUM_F];

    // ---- load + reduce: field f = tid>>3, 8 threads per field, 8 floats/row ----
    const int f   = tid >> 3;
    const int sub = tid & 7;
    const int off = f * EMBED + sub * 8;              // float index within a row

    const float* xb = x + (size_t)b0 * (NUM_F * EMBED);   // 2048 floats/row

    // four front-batched LDG.256, perfectly coalesced, 128B in flight per thread
    F8 a0 = ldg256(xb + off);
    F8 a1 = ldg256(xb + off + 1 * NUM_F * EMBED);
    F8 a2 = ldg256(xb + off + 2 * NUM_F * EMBED);
    F8 a3 = ldg256(xb + off + 3 * NUM_F * EMBED);

    float v0 = sum8(a0);
    float v1 = sum8(a1);
    float v2 = sum8(a2);
    float v3 = sum8(a3);

    // reduce across the 8 lanes of each field (independent chains overlap)
    v0 += __shfl_down_sync(0xffffffffu, v0, 4);
    v1 += __shfl_down_sync(0xffffffffu, v1, 4);
    v2 += __shfl_down_sync(0xffffffffu, v2, 4);
    v3 += __shfl_down_sync(0xffffffffu, v3, 4);
    v0 += __shfl_down_sync(0xffffffffu, v0, 2);
    v1 += __shfl_down_sync(0xffffffffu, v1, 2);
    v2 += __shfl_down_sync(0xffffffffu, v2, 2);
    v3 += __shfl_down_sync(0xffffffffu, v3, 2);
    v0 += __shfl_down_sync(0xffffffffu, v0, 1);
    v1 += __shfl_down_sync(0xffffffffu, v1, 1);
    v2 += __shfl_down_sync(0xffffffffu, v2, 1);
    v3 += __shfl_down_sync(0xffffffffu, v3, 1);
    if (sub == 0) { s[0][f] = v0; s[1][f] = v1; s[2][f] = v2; s[3][f] = v3; }
    __syncthreads();

    // ---- pairwise products: 2 iterations, 248/256 threads active each ----
    const int t = tid & 127;
    if (t < NPAIRS / 4) {
        int p = t * 4;

        // analytic p -> (i, j): start(i) = i*(63-i)/2, pairs ordered i asc, j asc
        float fi = (63.0f - sqrtf(3969.0f - 8.0f * (float)p)) * 0.5f;
        int i0 = (int)fi;
        int st = (i0 * (63 - i0)) >> 1;
        while (st > p)                           { --i0; st = (i0 * (63 - i0)) >> 1; }
        while (((i0 + 1) * (62 - i0)) >> 1 <= p) { ++i0; st = (i0 * (63 - i0)) >> 1; }
        const int j0 = i0 + 1 + (p - st);

        #pragma unroll
        for (int it = 0; it < 2; ++it) {
            const int r = (tid >> 7) + 2 * it;     // rows {0,1} then {2,3}
            const float* sr = s[r];
            int i = i0, j = j0;
            float4 rv;
            float* rp = &rv.x;
            #pragma unroll
            for (int k = 0; k < 4; ++k) {
                rp[k] = sr[i] * sr[j];
                ++j;
                if (j == NUM_F) { ++i; j = i + 1; }
            }
            out[(size_t)(b0 + r) * (NPAIRS / 4) + t] = rv;
        }
    }
}

extern "C" void kernel_launch(void* const* d_in, const int* in_sizes, int n_in,
                              void* d_out, int out_size)
{
    const float* x   = (const float*)d_in[0];
    float4*      out = (float4*)d_out;
    opn_kernel<<<BATCH / ROWS_CTA, THREADS>>>(x, out);
}

// round 17
// speedup vs baseline: 1.0011x; 1.0011x over previous
#include <cuda_runtime.h>
#include <math.h>

// Problem constants
#define BATCH     16384
#define NUM_F     32
#define EMBED     64
#define NPAIRS    496          // 32*31/2
#define THREADS   256
#define ROWS_CTA  2

// ---- plain 256-bit load/store (sm_103 LDG.256/STG.256), no cache hints ----
struct F8 { float v[8]; };

__device__ __forceinline__ F8 ldg256(const float* p) {
    unsigned r0,r1,r2,r3,r4,r5,r6,r7;
    asm("ld.global.nc.v8.b32 {%0,%1,%2,%3,%4,%5,%6,%7}, [%8];"
        : "=r"(r0),"=r"(r1),"=r"(r2),"=r"(r3),"=r"(r4),"=r"(r5),"=r"(r6),"=r"(r7)
        : "l"(p));
    F8 o;
    o.v[0]=__uint_as_float(r0); o.v[1]=__uint_as_float(r1);
    o.v[2]=__uint_as_float(r2); o.v[3]=__uint_as_float(r3);
    o.v[4]=__uint_as_float(r4); o.v[5]=__uint_as_float(r5);
    o.v[6]=__uint_as_float(r6); o.v[7]=__uint_as_float(r7);
    return o;
}

__device__ __forceinline__ void stg256(float* p, const F8& a) {
    asm volatile("st.global.v8.b32 [%0], {%1,%2,%3,%4,%5,%6,%7,%8};"
        :: "l"(p),
           "r"(__float_as_uint(a.v[0])), "r"(__float_as_uint(a.v[1])),
           "r"(__float_as_uint(a.v[2])), "r"(__float_as_uint(a.v[3])),
           "r"(__float_as_uint(a.v[4])), "r"(__float_as_uint(a.v[5])),
           "r"(__float_as_uint(a.v[6])), "r"(__float_as_uint(a.v[7]))
        : "memory");
}

__device__ __forceinline__ float sum8(const F8& a) {
    return ((a.v[0]+a.v[1]) + (a.v[2]+a.v[3])) + ((a.v[4]+a.v[5]) + (a.v[6]+a.v[7]));
}

// x: [BATCH, 32, 64] f32  (2048 floats per row)
// out: [BATCH, 496] f32   -> row is 1984 bytes = 62 * 32B (every row 32B-aligned)
__global__ __launch_bounds__(THREADS, 8)
void opn_kernel(const float* __restrict__ x, float* __restrict__ out)
{
    const int tid = threadIdx.x;
    const int b0  = blockIdx.x * ROWS_CTA;

    __shared__ float s[ROWS_CTA][NUM_F];

    // ---- load + reduce: field f = tid>>3, 8 threads per field, 8 floats/row ----
    const int f   = tid >> 3;
    const int sub = tid & 7;
    const int off = f * EMBED + sub * 8;              // float index within a row

    const float* xb0 = x + (size_t)b0 * (NUM_F * EMBED);   // 2048 floats/row
    const float* xb1 = xb0 + (NUM_F * EMBED);

    // two front-batched LDG.256, perfectly coalesced, 64B in flight per thread
    F8 a = ldg256(xb0 + off);
    F8 c = ldg256(xb1 + off);

    float v0 = sum8(a);
    float v1 = sum8(c);

    // reduce across the 8 lanes of each field (independent chains overlap)
    v0 += __shfl_down_sync(0xffffffffu, v0, 4);
    v1 += __shfl_down_sync(0xffffffffu, v1, 4);
    v0 += __shfl_down_sync(0xffffffffu, v0, 2);
    v1 += __shfl_down_sync(0xffffffffu, v1, 2);
    v0 += __shfl_down_sync(0xffffffffu, v0, 1);
    v1 += __shfl_down_sync(0xffffffffu, v1, 1);
    if (sub == 0) { s[0][f] = v0; s[1][f] = v1; }
    __syncthreads();

    // ---- pairwise products: 62 STG.256 per row; threads 0..61 -> row0, 128..189 -> row1 ----
    const int r = tid >> 7;          // 0 or 1
    const int t = tid & 127;
    if (t < NPAIRS / 8) {
        int p = t * 8;

        // analytic p -> (i, j): start(i) = i*(63-i)/2, pairs ordered i asc, j asc
        float fi = (63.0f - sqrtf(3969.0f - 8.0f * (float)p)) * 0.5f;
        int i = (int)fi;
        // integer fix-up against float rounding
        int st = (i * (63 - i)) >> 1;
        while (st > p)                         { --i; st = (i * (63 - i)) >> 1; }
        while (((i + 1) * (62 - i)) >> 1 <= p) { ++i; st = (i * (63 - i)) >> 1; }
        int j = i + 1 + (p - st);

        const float* sr = s[r];
        F8 rv;
        #pragma unroll
        for (int k = 0; k < 8; ++k) {
            rv.v[k] = sr[i] * sr[j];
            ++j;
            if (j == NUM_F) { ++i; j = i + 1; }
        }
        stg256(out + (size_t)(b0 + r) * NPAIRS + p, rv);
    }
}

extern "C" void kernel_launch(void* const* d_in, const int* in_sizes, int n_in,
                              void* d_out, int out_size)
{
    const float* x   = (const float*)d_in[0];
    float*       out = (float*)d_out;
    opn_kernel<<<BATCH / ROWS_CTA, THREADS>>>(x, out);
}